// round 1
// baseline (speedup 1.0000x reference)
#include <cuda_runtime.h>
#include <cuda_fp16.h>
#include <cstdint>

#define B_ROWS 32768
#define D1 1024
#define D2 512
#define KTOT 1536
#define OUTD 1024
#define NPACK 2048

#define BM 128
#define BN 128
#define BK 32
#define LDK 40   // 32 + 8 halves pad (16B-aligned rows, conflict-free frag loads)

// scratch (allocation-free rule: __device__ globals)
__device__ __half g_f[(size_t)B_ROWS * KTOT];   // 96 MB fused activations [B,1536]
__device__ __half g_w[(size_t)NPACK * KTOT];    // 6 MB packed W^T [2048,1536]

__device__ __forceinline__ float leaky(float x) { return x >= 0.f ? x : 0.01f * x; }

// ---------------------------------------------------------------------------
// Kernel 1: LayerNorm + leaky_relu for both streams, write fp16 into g_f.
// One block per row, 256 threads.
// ---------------------------------------------------------------------------
__global__ void ln_act_kernel(const float* __restrict__ x1, const float* __restrict__ x2,
                              const float* __restrict__ s1, const float* __restrict__ b1,
                              const float* __restrict__ s2, const float* __restrict__ b2) {
    int row = blockIdx.x;
    int tid = threadIdx.x;
    int lane = tid & 31, warp = tid >> 5;
    __shared__ float red[16];
    __shared__ float stats[4];

    // ---- stream 1: 1024 floats, one float4 per thread ----
    float4 v = reinterpret_cast<const float4*>(x1 + (size_t)row * D1)[tid];
    float s = v.x + v.y + v.z + v.w;
    float q = v.x*v.x + v.y*v.y + v.z*v.z + v.w*v.w;
#pragma unroll
    for (int o = 16; o; o >>= 1) {
        s += __shfl_down_sync(0xffffffffu, s, o);
        q += __shfl_down_sync(0xffffffffu, q, o);
    }
    if (lane == 0) { red[warp] = s; red[8 + warp] = q; }
    __syncthreads();
    if (tid == 0) {
        float a = 0.f, b = 0.f;
#pragma unroll
        for (int i = 0; i < 8; i++) { a += red[i]; b += red[8 + i]; }
        float m = a * (1.f / D1);
        stats[0] = m;
        stats[1] = rsqrtf(b * (1.f / D1) - m * m + 1e-6f);
    }
    __syncthreads();
    {
        float m = stats[0], inv = stats[1];
        float4 sc = reinterpret_cast<const float4*>(s1)[tid];
        float4 bi = reinterpret_cast<const float4*>(b1)[tid];
        float y0 = leaky((v.x - m) * inv * sc.x + bi.x);
        float y1 = leaky((v.y - m) * inv * sc.y + bi.y);
        float y2 = leaky((v.z - m) * inv * sc.z + bi.z);
        float y3 = leaky((v.w - m) * inv * sc.w + bi.w);
        __half2* dst = reinterpret_cast<__half2*>(g_f + (size_t)row * KTOT);
        dst[tid * 2]     = __floats2half2_rn(y0, y1);
        dst[tid * 2 + 1] = __floats2half2_rn(y2, y3);
    }

    // ---- stream 2: 512 floats, threads 0..127 ----
    float4 w = make_float4(0.f, 0.f, 0.f, 0.f);
    float s2v = 0.f, q2 = 0.f;
    if (tid < 128) {
        w = reinterpret_cast<const float4*>(x2 + (size_t)row * D2)[tid];
        s2v = w.x + w.y + w.z + w.w;
        q2 = w.x*w.x + w.y*w.y + w.z*w.z + w.w*w.w;
    }
#pragma unroll
    for (int o = 16; o; o >>= 1) {
        s2v += __shfl_down_sync(0xffffffffu, s2v, o);
        q2  += __shfl_down_sync(0xffffffffu, q2, o);
    }
    if (lane == 0) { red[warp] = s2v; red[8 + warp] = q2; }
    __syncthreads();
    if (tid == 0) {
        float a = 0.f, b = 0.f;
#pragma unroll
        for (int i = 0; i < 8; i++) { a += red[i]; b += red[8 + i]; }
        float m = a * (1.f / D2);
        stats[2] = m;
        stats[3] = rsqrtf(b * (1.f / D2) - m * m + 1e-6f);
    }
    __syncthreads();
    if (tid < 128) {
        float m = stats[2], inv = stats[3];
        float4 sc = reinterpret_cast<const float4*>(s2)[tid];
        float4 bi = reinterpret_cast<const float4*>(b2)[tid];
        float y0 = leaky((w.x - m) * inv * sc.x + bi.x);
        float y1 = leaky((w.y - m) * inv * sc.y + bi.y);
        float y2 = leaky((w.z - m) * inv * sc.z + bi.z);
        float y3 = leaky((w.w - m) * inv * sc.w + bi.w);
        __half2* dst = reinterpret_cast<__half2*>(g_f + (size_t)row * KTOT + D1);
        dst[tid * 2]     = __floats2half2_rn(y0, y1);
        dst[tid * 2 + 1] = __floats2half2_rn(y2, y3);
    }
}

// ---------------------------------------------------------------------------
// Kernel 2: pack weights to fp16, K-transposed, out/gate interleaved by 16 cols.
// Packed column c: q = c/32, r = c%32; output column n' = q*16 + (r%16);
// r<16 -> out-Dense weight, r>=16 -> gate-Dense weight.
// g_w[c][k] layout = [NPACK][KTOT] (k contiguous) so GEMM B-tile loads need no
// transpose and b-fragment k-pairs are contiguous.
// ---------------------------------------------------------------------------
__global__ void pack_w_kernel(const float* __restrict__ Wo1, const float* __restrict__ Wo2,
                              const float* __restrict__ Wg1, const float* __restrict__ Wg2) {
    int idx = blockIdx.x * blockDim.x + threadIdx.x;   // NPACK*KTOT threads
    int c = idx % NPACK;
    int k = idx / NPACK;
    int qq = c >> 5, r = c & 31;
    int n = qq * 16 + (r & 15);
    const float* W;
    int kk;
    if (k < D1) { kk = k;      W = (r < 16) ? Wo1 : Wg1; }
    else        { kk = k - D1; W = (r < 16) ? Wo2 : Wg2; }
    g_w[(size_t)c * KTOT + k] = __float2half_rn(W[(size_t)kk * OUTD + n]);
}

// ---------------------------------------------------------------------------
// Kernel 3: fused GEMM + gate epilogue.
// C[B,2048] = f @ Wpack; per-warp acc tile holds paired out/gate columns, so
// epilogue computes out = sigmoid(acc_g + bg) * (acc_o + bo) in registers.
// ---------------------------------------------------------------------------
__device__ __forceinline__ void mma16816(float* c, const uint32_t* a, const uint32_t* b) {
    asm volatile(
        "mma.sync.aligned.m16n8k16.row.col.f32.f16.f16.f32 "
        "{%0,%1,%2,%3}, {%4,%5,%6,%7}, {%8,%9}, {%0,%1,%2,%3};\n"
        : "+f"(c[0]), "+f"(c[1]), "+f"(c[2]), "+f"(c[3])
        : "r"(a[0]), "r"(a[1]), "r"(a[2]), "r"(a[3]), "r"(b[0]), "r"(b[1]));
}

__global__ __launch_bounds__(256, 1) void gemm_kernel(
    const float* __restrict__ bo1, const float* __restrict__ bo2,
    const float* __restrict__ bg1, const float* __restrict__ bg2,
    float* __restrict__ out) {
    __shared__ __half As[2][BM][LDK];
    __shared__ __half Bs[2][BN][LDK];

    // m-chunked raster: 64 m-tiles x 16 n-tiles per chunk -> A panel L2-resident
    const int NT = NPACK / BN;   // 16
    const int MC = 64;
    int id = blockIdx.x;
    int chunk = id / (NT * MC);
    int rem = id - chunk * (NT * MC);
    int ntile = rem / MC;
    int mtile = chunk * MC + (rem - ntile * MC);
    int m0 = mtile * BM;
    int c0 = ntile * BN;

    int tid = threadIdx.x;
    int lrow = tid >> 2;            // 0..63
    int lk = (tid & 3) * 8;         // 16B chunk within k

    const __half* Ag = g_f + (size_t)(m0 + lrow) * KTOT + lk;
    const __half* Bg = g_w + (size_t)(c0 + lrow) * KTOT + lk;

    uint32_t sA0 = (uint32_t)__cvta_generic_to_shared(&As[0][lrow][lk]);
    uint32_t sA1 = (uint32_t)__cvta_generic_to_shared(&As[0][lrow + 64][lk]);
    uint32_t sB0 = (uint32_t)__cvta_generic_to_shared(&Bs[0][lrow][lk]);
    uint32_t sB1 = (uint32_t)__cvta_generic_to_shared(&Bs[0][lrow + 64][lk]);
    const uint32_t stageBytes = BM * LDK * 2;

#define CPA(dst, src) \
    asm volatile("cp.async.cg.shared.global [%0], [%1], 16;\n" :: "r"(dst), "l"(src) : "memory")

    int warp = tid >> 5, lane = tid & 31;
    int wm = (warp & 1) * 64;
    int wn = (warp >> 1) * 32;
    int g = lane >> 2, t = lane & 3;

    float acc[4][4][4];
#pragma unroll
    for (int i = 0; i < 4; i++)
#pragma unroll
        for (int j = 0; j < 4; j++)
#pragma unroll
            for (int e = 0; e < 4; e++) acc[i][j][e] = 0.f;

    // prologue: stage 0
    {
        CPA(sA0, Ag); CPA(sA1, Ag + (size_t)64 * KTOT);
        CPA(sB0, Bg); CPA(sB1, Bg + (size_t)64 * KTOT);
        asm volatile("cp.async.commit_group;\n" ::: "memory");
    }

    const int KIT = KTOT / BK;   // 48
    for (int kt = 0; kt < KIT; kt++) {
        if (kt + 1 < KIT) {
            uint32_t off = ((kt + 1) & 1) * stageBytes;
            int k0 = (kt + 1) * BK;
            CPA(sA0 + off, Ag + k0); CPA(sA1 + off, Ag + k0 + (size_t)64 * KTOT);
            CPA(sB0 + off, Bg + k0); CPA(sB1 + off, Bg + k0 + (size_t)64 * KTOT);
            asm volatile("cp.async.commit_group;\n" ::: "memory");
            asm volatile("cp.async.wait_group 1;\n" ::: "memory");
        } else {
            asm volatile("cp.async.wait_group 0;\n" ::: "memory");
        }
        __syncthreads();
        int s = kt & 1;
#pragma unroll
        for (int ks = 0; ks < 2; ks++) {
            int k0 = ks * 16;
            uint32_t af[4][4], bf[4][2];
#pragma unroll
            for (int mi = 0; mi < 4; mi++) {
                int r = wm + mi * 16;
                af[mi][0] = *(const uint32_t*)&As[s][r + g][k0 + t * 2];
                af[mi][1] = *(const uint32_t*)&As[s][r + g + 8][k0 + t * 2];
                af[mi][2] = *(const uint32_t*)&As[s][r + g][k0 + t * 2 + 8];
                af[mi][3] = *(const uint32_t*)&As[s][r + g + 8][k0 + t * 2 + 8];
            }
#pragma unroll
            for (int nj = 0; nj < 4; nj++) {
                int r = wn + nj * 8 + g;
                bf[nj][0] = *(const uint32_t*)&Bs[s][r][k0 + t * 2];
                bf[nj][1] = *(const uint32_t*)&Bs[s][r][k0 + t * 2 + 8];
            }
#pragma unroll
            for (int mi = 0; mi < 4; mi++)
#pragma unroll
                for (int nj = 0; nj < 4; nj++)
                    mma16816(acc[mi][nj], af[mi], bf[nj]);
        }
        __syncthreads();
    }

    // fused epilogue: nj 0,1 = out-acc (cols 0..15 of warp q-group),
    // nj 2,3 = gate-acc for the same output columns.
    int ncolbase = ((c0 + wn) >> 5) * 16;
#pragma unroll
    for (int mi = 0; mi < 4; mi++) {
#pragma unroll
        for (int j = 0; j < 2; j++) {
#pragma unroll
            for (int e = 0; e < 4; e++) {
                int n = ncolbase + j * 8 + t * 2 + (e & 1);
                int m = m0 + wm + mi * 16 + g + ((e >> 1) * 8);
                float o  = acc[mi][j][e]     + bo1[n] + bo2[n];
                float gg = acc[mi][j + 2][e] + bg1[n] + bg2[n];
                out[(size_t)m * OUTD + n] = o * (1.f / (1.f + __expf(-gg)));
            }
        }
    }
#undef CPA
}

// ---------------------------------------------------------------------------
extern "C" void kernel_launch(void* const* d_in, const int* in_sizes, int n_in,
                              void* d_out, int out_size) {
    const float* x1  = (const float*)d_in[0];
    const float* x2  = (const float*)d_in[1];
    const float* s1  = (const float*)d_in[2];
    const float* b1  = (const float*)d_in[3];
    const float* s2  = (const float*)d_in[4];
    const float* b2  = (const float*)d_in[5];
    const float* Wo1 = (const float*)d_in[6];
    const float* bo1 = (const float*)d_in[7];
    const float* Wo2 = (const float*)d_in[8];
    const float* bo2 = (const float*)d_in[9];
    const float* Wg1 = (const float*)d_in[10];
    const float* bg1 = (const float*)d_in[11];
    const float* Wg2 = (const float*)d_in[12];
    const float* bg2 = (const float*)d_in[13];
    float* out = (float*)d_out;

    ln_act_kernel<<<B_ROWS, 256>>>(x1, x2, s1, b1, s2, b2);
    pack_w_kernel<<<(NPACK * KTOT) / 256, 256>>>(Wo1, Wo2, Wg1, Wg2);
    gemm_kernel<<<(B_ROWS / BM) * (NPACK / BN), 256>>>(bo1, bo2, bg1, bg2, out);
}

// round 3
// speedup vs baseline: 1.3923x; 1.3923x over previous
#include <cuda_runtime.h>
#include <cuda_fp16.h>
#include <cstdint>

#define B_ROWS 32768
#define D1 1024
#define D2 512
#define KTOT 1536
#define OUTD 1024
#define NPACK 2048

// scratch (allocation-free rule: __device__ globals); 16B+ alignment for cp.async
__device__ __align__(128) __half g_f[(size_t)B_ROWS * KTOT];  // 96 MB activations
__device__ __align__(128) __half g_w[(size_t)NPACK * KTOT];   // 6 MB packed W^T

__device__ __forceinline__ float leaky(float x) { return x >= 0.f ? x : 0.01f * x; }

// ---------------------------------------------------------------------------
// Kernel 1: LayerNorm + leaky_relu, warp-per-row, shfl-only reductions.
// ---------------------------------------------------------------------------
__global__ void __launch_bounds__(256) ln_act_kernel(
    const float* __restrict__ x1, const float* __restrict__ x2,
    const float* __restrict__ s1, const float* __restrict__ b1,
    const float* __restrict__ s2, const float* __restrict__ b2) {
    int lane = threadIdx.x & 31;
    int row = blockIdx.x * 8 + (threadIdx.x >> 5);

    // stream 1: 1024 floats = 8 float4 per lane
    const float4* xr = reinterpret_cast<const float4*>(x1 + (size_t)row * D1);
    float4 v[8];
    float s = 0.f, q = 0.f;
#pragma unroll
    for (int j = 0; j < 8; j++) {
        v[j] = xr[lane + 32 * j];
        s += v[j].x + v[j].y + v[j].z + v[j].w;
        q += v[j].x*v[j].x + v[j].y*v[j].y + v[j].z*v[j].z + v[j].w*v[j].w;
    }
#pragma unroll
    for (int o = 16; o; o >>= 1) {
        s += __shfl_xor_sync(0xffffffffu, s, o);
        q += __shfl_xor_sync(0xffffffffu, q, o);
    }
    float m = s * (1.f / D1);
    float inv = rsqrtf(q * (1.f / D1) - m * m + 1e-6f);
    __half2* dst = reinterpret_cast<__half2*>(g_f + (size_t)row * KTOT);
#pragma unroll
    for (int j = 0; j < 8; j++) {
        int f = lane + 32 * j;
        float4 sc = reinterpret_cast<const float4*>(s1)[f];
        float4 bi = reinterpret_cast<const float4*>(b1)[f];
        float y0 = leaky((v[j].x - m) * inv * sc.x + bi.x);
        float y1 = leaky((v[j].y - m) * inv * sc.y + bi.y);
        float y2 = leaky((v[j].z - m) * inv * sc.z + bi.z);
        float y3 = leaky((v[j].w - m) * inv * sc.w + bi.w);
        dst[2 * f]     = __floats2half2_rn(y0, y1);
        dst[2 * f + 1] = __floats2half2_rn(y2, y3);
    }

    // stream 2: 512 floats = 4 float4 per lane
    const float4* xr2 = reinterpret_cast<const float4*>(x2 + (size_t)row * D2);
    float4 w[4];
    s = 0.f; q = 0.f;
#pragma unroll
    for (int j = 0; j < 4; j++) {
        w[j] = xr2[lane + 32 * j];
        s += w[j].x + w[j].y + w[j].z + w[j].w;
        q += w[j].x*w[j].x + w[j].y*w[j].y + w[j].z*w[j].z + w[j].w*w[j].w;
    }
#pragma unroll
    for (int o = 16; o; o >>= 1) {
        s += __shfl_xor_sync(0xffffffffu, s, o);
        q += __shfl_xor_sync(0xffffffffu, q, o);
    }
    float m2 = s * (1.f / D2);
    float inv2 = rsqrtf(q * (1.f / D2) - m2 * m2 + 1e-6f);
    __half2* dst2 = reinterpret_cast<__half2*>(g_f + (size_t)row * KTOT + D1);
#pragma unroll
    for (int j = 0; j < 4; j++) {
        int f = lane + 32 * j;
        float4 sc = reinterpret_cast<const float4*>(s2)[f];
        float4 bi = reinterpret_cast<const float4*>(b2)[f];
        float y0 = leaky((w[j].x - m2) * inv2 * sc.x + bi.x);
        float y1 = leaky((w[j].y - m2) * inv2 * sc.y + bi.y);
        float y2 = leaky((w[j].z - m2) * inv2 * sc.z + bi.z);
        float y3 = leaky((w[j].w - m2) * inv2 * sc.w + bi.w);
        dst2[2 * f]     = __floats2half2_rn(y0, y1);
        dst2[2 * f + 1] = __floats2half2_rn(y2, y3);
    }
}

// ---------------------------------------------------------------------------
// Kernel 2: pack weights fp16 K-transposed, out/gate interleaved per 32 cols,
// transposed through smem so global writes are coalesced.
// packed col c: q=c>>5, r=c&31, n = q*16+(r&15); r<16 -> W_out else W_g.
// ---------------------------------------------------------------------------
__global__ void __launch_bounds__(256) pack_w_kernel(
    const float* __restrict__ Wo1, const float* __restrict__ Wo2,
    const float* __restrict__ Wg1, const float* __restrict__ Wg2) {
    __shared__ __half smp[32][40];
    int q = blockIdx.x;        // 0..63 column group
    int kt = blockIdx.y;       // 0..47 k tile of 32
    int t = threadIdx.x;
    int r = t & 31;
    int kk = t >> 5;           // 0..7
    int k0 = kt * 32;
    const float* W;
    int kbase;
    if (k0 < D1) { W = (r < 16) ? Wo1 : Wg1; kbase = k0; }
    else         { W = (r < 16) ? Wo2 : Wg2; kbase = k0 - D1; }
    int n = q * 16 + (r & 15);
#pragma unroll
    for (int p = 0; p < 4; p++) {
        int kl = kk + 8 * p;
        smp[r][kl] = __float2half_rn(W[(size_t)(kbase + kl) * OUTD + n]);
    }
    __syncthreads();
    int r2 = t >> 3, j = t & 7;
    uint2 val = *reinterpret_cast<uint2*>(&smp[r2][j * 4]);
    *reinterpret_cast<uint2*>(&g_w[(size_t)(q * 32 + r2) * KTOT + k0 + j * 4]) = val;
}

// ---------------------------------------------------------------------------
// Kernel 3: mma.sync GEMM 256x128(packed) x K=1536, 512 thr, 16 warps (64x32),
// BK=64, 3-stage cp.async, ldmatrix.x4, fused sigmoid-gate epilogue.
// ---------------------------------------------------------------------------
#define BK 64
#define KIT (KTOT / BK)          // 24
#define ST_A 32768               // 256 rows x 128B
#define ST_B 16384               // 128 rows x 128B
#define ST_STRIDE (ST_A + ST_B)  // 49152
#define SMEM_DYN (3 * ST_STRIDE) // 147456

__device__ __forceinline__ uint32_t smem_u32(const void* p) {
    uint32_t a;
    asm("{ .reg .u64 t; cvta.to.shared.u64 t, %1; cvt.u32.u64 %0, t; }" : "=r"(a) : "l"(p));
    return a;
}
__device__ __forceinline__ void mma16816(float* c, const uint32_t* a, const uint32_t* b) {
    asm volatile(
        "mma.sync.aligned.m16n8k16.row.col.f32.f16.f16.f32 "
        "{%0,%1,%2,%3}, {%4,%5,%6,%7}, {%8,%9}, {%0,%1,%2,%3};\n"
        : "+f"(c[0]), "+f"(c[1]), "+f"(c[2]), "+f"(c[3])
        : "r"(a[0]), "r"(a[1]), "r"(a[2]), "r"(a[3]), "r"(b[0]), "r"(b[1]));
}
#define LDSM4(r0, r1, r2, r3, addr) \
    asm volatile("ldmatrix.sync.aligned.m8n8.x4.shared.b16 {%0,%1,%2,%3}, [%4];\n" \
                 : "=r"(r0), "=r"(r1), "=r"(r2), "=r"(r3) : "r"(addr))
#define CPA16(dst, src) \
    asm volatile("cp.async.cg.shared.global [%0], [%1], 16;" :: "r"(dst), "l"(src) : "memory")
#define CP_COMMIT() asm volatile("cp.async.commit_group;" ::: "memory")

__global__ void __launch_bounds__(512, 1) gemm_kernel(
    const float* __restrict__ bo1, const float* __restrict__ bo2,
    const float* __restrict__ bg1, const float* __restrict__ bg2,
    float* __restrict__ out) {
    extern __shared__ char sm[];
    uint32_t base = smem_u32(sm);

    // raster: chunks of 16 mtiles x 16 ntiles (~A+B L2-resident per wave)
    int id = blockIdx.x;
    int chunk = id >> 8;
    int rem = id & 255;
    int ntile = rem >> 4;
    int mtile = chunk * 16 + (rem & 15);
    int m0 = mtile * 256;
    int c0 = ntile * 128;

    int tid = threadIdx.x;
    int warp = tid >> 5, lane = tid & 31;
    int wm = (warp & 3) * 64;
    int wn = (warp >> 2) * 32;

    // cp.async assignments
    uint32_t aDst[4], bDst[2];
    const __half* aSrc[4];
    const __half* bSrc[2];
#pragma unroll
    for (int i = 0; i < 4; i++) {
        int idx = tid + 512 * i;            // 0..2047
        int row = idx >> 3, c = idx & 7;
        aDst[i] = base + (uint32_t)(row * 128 + ((c ^ (row & 7)) * 16));
        aSrc[i] = g_f + (size_t)(m0 + row) * KTOT + c * 8;
    }
#pragma unroll
    for (int i = 0; i < 2; i++) {
        int idx = tid + 512 * i;            // 0..1023
        int row = idx >> 3, c = idx & 7;
        bDst[i] = base + ST_A + (uint32_t)(row * 128 + ((c ^ (row & 7)) * 16));
        bSrc[i] = g_w + (size_t)(c0 + row) * KTOT + c * 8;
    }

#define LOAD_STAGE(j) do { \
        uint32_t _so = (uint32_t)((j) % 3) * ST_STRIDE; \
        size_t _ko = (size_t)(j) * BK; \
        _Pragma("unroll") \
        for (int _i = 0; _i < 4; _i++) CPA16(aDst[_i] + _so, aSrc[_i] + _ko); \
        _Pragma("unroll") \
        for (int _i = 0; _i < 2; _i++) CPA16(bDst[_i] + _so, bSrc[_i] + _ko); \
        CP_COMMIT(); \
    } while (0)

    // ldmatrix address components (xor term is lane&7 since wm,wn are 8-aligned)
    uint32_t xorv = lane & 7;
    uint32_t aRowOff = (uint32_t)(wm + (lane & 15)) * 128;
    uint32_t aSel = lane >> 4;                       // k8 selector
    uint32_t bRowOff = (uint32_t)(wn + ((lane >> 4) << 3) + (lane & 7)) * 128;
    uint32_t bSel = (lane >> 3) & 1;

    float acc[4][4][4];
#pragma unroll
    for (int i = 0; i < 4; i++)
#pragma unroll
        for (int j = 0; j < 4; j++)
#pragma unroll
            for (int e = 0; e < 4; e++) acc[i][j][e] = 0.f;

    LOAD_STAGE(0);
    LOAD_STAGE(1);

    for (int kt = 0; kt < KIT; kt++) {
        asm volatile("cp.async.wait_group 1;" ::: "memory");
        __syncthreads();
        if (kt + 2 < KIT) { LOAD_STAGE(kt + 2); }
        else { CP_COMMIT(); }   // keep group count uniform

        uint32_t stA = base + (uint32_t)(kt % 3) * ST_STRIDE;
        uint32_t stB = stA + ST_A;
#pragma unroll
        for (int ks = 0; ks < 4; ks++) {
            uint32_t a[4][4], b[4][2];
            uint32_t physA = ((2u * ks + aSel) ^ xorv) << 4;
            uint32_t physB = ((2u * ks + bSel) ^ xorv) << 4;
#pragma unroll
            for (int mi = 0; mi < 4; mi++)
                LDSM4(a[mi][0], a[mi][1], a[mi][2], a[mi][3],
                      stA + aRowOff + mi * 2048 + physA);
            LDSM4(b[0][0], b[0][1], b[1][0], b[1][1], stB + bRowOff + physB);
            LDSM4(b[2][0], b[2][1], b[3][0], b[3][1], stB + bRowOff + 2048 + physB);
#pragma unroll
            for (int mi = 0; mi < 4; mi++)
#pragma unroll
                for (int nj = 0; nj < 4; nj++)
                    mma16816(acc[mi][nj], a[mi], b[nj]);
        }
    }
    __syncthreads();   // stage smem now reusable as epilogue staging

    // epilogue: gate in registers -> smem (stride 68) -> coalesced float4 out
    float* ep = reinterpret_cast<float*>(sm);
    {
        int g = lane >> 2, t = lane & 3;
#pragma unroll
        for (int j = 0; j < 2; j++) {
#pragma unroll
            for (int e = 0; e < 4; e++) {
                int nl = (wn >> 1) + j * 8 + t * 2 + (e & 1);
                int n = ntile * 64 + nl;
                float bo = __ldg(bo1 + n) + __ldg(bo2 + n);
                float bg = __ldg(bg1 + n) + __ldg(bg2 + n);
#pragma unroll
                for (int mi = 0; mi < 4; mi++) {
                    int ml = wm + mi * 16 + g + ((e >> 1) * 8);
                    float o = acc[mi][j][e] + bo;
                    float gg = acc[mi][j + 2][e] + bg;
                    ep[ml * 68 + nl] = o * (1.f / (1.f + __expf(-gg)));
                }
            }
        }
    }
    __syncthreads();
    {
        float* outp = out + (size_t)m0 * OUTD + ntile * 64;
#pragma unroll
        for (int qq = 0; qq < 8; qq++) {
            int idx = tid + 512 * qq;        // 4096 float4 (256 rows x 16)
            int row = idx >> 4, c = (idx & 15) * 4;
            const float* src = ep + row * 68 + c;
            float4 v = make_float4(src[0], src[1], src[2], src[3]);
            *reinterpret_cast<float4*>(outp + (size_t)row * OUTD + c) = v;
        }
    }
#undef LOAD_STAGE
}

// ---------------------------------------------------------------------------
extern "C" void kernel_launch(void* const* d_in, const int* in_sizes, int n_in,
                              void* d_out, int out_size) {
    const float* x1  = (const float*)d_in[0];
    const float* x2  = (const float*)d_in[1];
    const float* s1  = (const float*)d_in[2];
    const float* b1  = (const float*)d_in[3];
    const float* s2  = (const float*)d_in[4];
    const float* b2  = (const float*)d_in[5];
    const float* Wo1 = (const float*)d_in[6];
    const float* bo1 = (const float*)d_in[7];
    const float* Wo2 = (const float*)d_in[8];
    const float* bo2 = (const float*)d_in[9];
    const float* Wg1 = (const float*)d_in[10];
    const float* bg1 = (const float*)d_in[11];
    const float* Wg2 = (const float*)d_in[12];
    const float* bg2 = (const float*)d_in[13];
    float* out = (float*)d_out;

    ln_act_kernel<<<B_ROWS / 8, 256>>>(x1, x2, s1, b1, s2, b2);
    pack_w_kernel<<<dim3(64, 48), 256>>>(Wo1, Wo2, Wg1, Wg2);

    static int attr_set = 0;
    if (!attr_set) {
        cudaFuncSetAttribute(gemm_kernel,
                             cudaFuncAttributeMaxDynamicSharedMemorySize, SMEM_DYN);
        attr_set = 1;
    }
    gemm_kernel<<<(B_ROWS / 256) * (NPACK / 128), 512, SMEM_DYN>>>(
        bo1, bo2, bg1, bg2, out);
}

// round 4
// speedup vs baseline: 1.5443x; 1.1092x over previous
#include <cuda_runtime.h>
#include <cuda_fp16.h>
#include <cstdint>

#define B_ROWS 32768
#define D1 1024
#define D2 512
#define KTOT 1536
#define OUTD 1024
#define NPACK 2048

// scratch (allocation-free rule: __device__ globals)
__device__ __align__(128) __half g_f[(size_t)B_ROWS * KTOT];  // 96 MB activations
__device__ __align__(128) __half g_w[(size_t)NPACK * KTOT];   // 6 MB packed W^T

__device__ __forceinline__ float leaky(float x) { return x >= 0.f ? x : 0.01f * x; }

// ---------------------------------------------------------------------------
// Kernel 1: LayerNorm + leaky_relu, warp-per-row, shfl-only; stream1 values
// re-read after reduction (L1/L2 hit) to halve register pressure -> 2x occ.
// ---------------------------------------------------------------------------
__global__ void __launch_bounds__(256) ln_act_kernel(
    const float* __restrict__ x1, const float* __restrict__ x2,
    const float* __restrict__ s1, const float* __restrict__ b1,
    const float* __restrict__ s2, const float* __restrict__ b2) {
    int lane = threadIdx.x & 31;
    int row = blockIdx.x * 8 + (threadIdx.x >> 5);

    // stream 1: pass 1 = moments only
    const float4* xr = reinterpret_cast<const float4*>(x1 + (size_t)row * D1);
    float s = 0.f, q = 0.f;
#pragma unroll
    for (int j = 0; j < 8; j++) {
        float4 t = xr[lane + 32 * j];
        s += t.x + t.y + t.z + t.w;
        q += t.x*t.x + t.y*t.y + t.z*t.z + t.w*t.w;
    }
#pragma unroll
    for (int o = 16; o; o >>= 1) {
        s += __shfl_xor_sync(0xffffffffu, s, o);
        q += __shfl_xor_sync(0xffffffffu, q, o);
    }
    float m = s * (1.f / D1);
    float inv = rsqrtf(q * (1.f / D1) - m * m + 1e-6f);
    // pass 2: re-read (cache hit), normalize, store fp16
    __half2* dst = reinterpret_cast<__half2*>(g_f + (size_t)row * KTOT);
#pragma unroll
    for (int j = 0; j < 8; j++) {
        int f = lane + 32 * j;
        float4 t = xr[f];
        float4 sc = reinterpret_cast<const float4*>(s1)[f];
        float4 bi = reinterpret_cast<const float4*>(b1)[f];
        float y0 = leaky((t.x - m) * inv * sc.x + bi.x);
        float y1 = leaky((t.y - m) * inv * sc.y + bi.y);
        float y2 = leaky((t.z - m) * inv * sc.z + bi.z);
        float y3 = leaky((t.w - m) * inv * sc.w + bi.w);
        dst[2 * f]     = __floats2half2_rn(y0, y1);
        dst[2 * f + 1] = __floats2half2_rn(y2, y3);
    }

    // stream 2: 4 float4 per lane (kept in regs)
    const float4* xr2 = reinterpret_cast<const float4*>(x2 + (size_t)row * D2);
    float4 w[4];
    s = 0.f; q = 0.f;
#pragma unroll
    for (int j = 0; j < 4; j++) {
        w[j] = xr2[lane + 32 * j];
        s += w[j].x + w[j].y + w[j].z + w[j].w;
        q += w[j].x*w[j].x + w[j].y*w[j].y + w[j].z*w[j].z + w[j].w*w[j].w;
    }
#pragma unroll
    for (int o = 16; o; o >>= 1) {
        s += __shfl_xor_sync(0xffffffffu, s, o);
        q += __shfl_xor_sync(0xffffffffu, q, o);
    }
    float m2 = s * (1.f / D2);
    float inv2 = rsqrtf(q * (1.f / D2) - m2 * m2 + 1e-6f);
    __half2* dst2 = reinterpret_cast<__half2*>(g_f + (size_t)row * KTOT + D1);
#pragma unroll
    for (int j = 0; j < 4; j++) {
        int f = lane + 32 * j;
        float4 sc = reinterpret_cast<const float4*>(s2)[f];
        float4 bi = reinterpret_cast<const float4*>(b2)[f];
        float y0 = leaky((w[j].x - m2) * inv2 * sc.x + bi.x);
        float y1 = leaky((w[j].y - m2) * inv2 * sc.y + bi.y);
        float y2 = leaky((w[j].z - m2) * inv2 * sc.z + bi.z);
        float y3 = leaky((w[j].w - m2) * inv2 * sc.w + bi.w);
        dst2[2 * f]     = __floats2half2_rn(y0, y1);
        dst2[2 * f + 1] = __floats2half2_rn(y2, y3);
    }
}

// ---------------------------------------------------------------------------
// Kernel 2: pack weights fp16 K-transposed, out/gate interleaved per 32 cols.
// packed col c: q=c>>5, r=c&31, n = q*16+(r&15); r<16 -> W_out else W_g.
// ---------------------------------------------------------------------------
__global__ void __launch_bounds__(256) pack_w_kernel(
    const float* __restrict__ Wo1, const float* __restrict__ Wo2,
    const float* __restrict__ Wg1, const float* __restrict__ Wg2) {
    __shared__ __half smp[32][40];
    int q = blockIdx.x;        // 0..63 column group
    int kt = blockIdx.y;       // 0..47 k tile of 32
    int t = threadIdx.x;
    int r = t & 31;
    int kk = t >> 5;
    int k0 = kt * 32;
    const float* W;
    int kbase;
    if (k0 < D1) { W = (r < 16) ? Wo1 : Wg1; kbase = k0; }
    else         { W = (r < 16) ? Wo2 : Wg2; kbase = k0 - D1; }
    int n = q * 16 + (r & 15);
#pragma unroll
    for (int p = 0; p < 4; p++) {
        int kl = kk + 8 * p;
        smp[r][kl] = __float2half_rn(W[(size_t)(kbase + kl) * OUTD + n]);
    }
    __syncthreads();
    int r2 = t >> 3, j = t & 7;
    uint2 val = *reinterpret_cast<uint2*>(&smp[r2][j * 4]);
    *reinterpret_cast<uint2*>(&g_w[(size_t)(q * 32 + r2) * KTOT + k0 + j * 4]) = val;
}

// ---------------------------------------------------------------------------
// Kernel 3: mma.sync GEMM 128x128(packed) x K=1536, 256 thr, 8 warps (64x32),
// 3-stage cp.async (96KB smem -> 2 CTAs/SM), ldmatrix.x4, fused gate epilogue.
// ---------------------------------------------------------------------------
#define BK 64
#define KIT (KTOT / BK)          // 24
#define ST_A 16384               // 128 rows x 128B
#define ST_B 16384
#define ST_STRIDE (ST_A + ST_B)  // 32768
#define SMEM_DYN (3 * ST_STRIDE) // 98304

__device__ __forceinline__ uint32_t smem_u32(const void* p) {
    uint32_t a;
    asm("{ .reg .u64 t; cvta.to.shared.u64 t, %1; cvt.u32.u64 %0, t; }" : "=r"(a) : "l"(p));
    return a;
}
__device__ __forceinline__ void mma16816(float* c, const uint32_t* a, const uint32_t* b) {
    asm volatile(
        "mma.sync.aligned.m16n8k16.row.col.f32.f16.f16.f32 "
        "{%0,%1,%2,%3}, {%4,%5,%6,%7}, {%8,%9}, {%0,%1,%2,%3};\n"
        : "+f"(c[0]), "+f"(c[1]), "+f"(c[2]), "+f"(c[3])
        : "r"(a[0]), "r"(a[1]), "r"(a[2]), "r"(a[3]), "r"(b[0]), "r"(b[1]));
}
#define LDSM4(r0, r1, r2, r3, addr) \
    asm volatile("ldmatrix.sync.aligned.m8n8.x4.shared.b16 {%0,%1,%2,%3}, [%4];\n" \
                 : "=r"(r0), "=r"(r1), "=r"(r2), "=r"(r3) : "r"(addr))
#define CPA16(dst, src) \
    asm volatile("cp.async.cg.shared.global [%0], [%1], 16;" :: "r"(dst), "l"(src) : "memory")
#define CP_COMMIT() asm volatile("cp.async.commit_group;" ::: "memory")

__global__ void __launch_bounds__(256, 2) gemm_kernel(
    const float* __restrict__ bo1, const float* __restrict__ bo2,
    const float* __restrict__ bg1, const float* __restrict__ bg2,
    float* __restrict__ out) {
    extern __shared__ char sm[];
    uint32_t base = smem_u32(sm);

    // raster: chunks of 32 mtiles x 16 ntiles -> A+B chunk L2-resident
    int id = blockIdx.x;
    int chunk = id >> 9;
    int rem = id & 511;
    int ntile = rem >> 5;
    int mtile = chunk * 32 + (rem & 31);
    int m0 = mtile * 128;
    int c0 = ntile * 128;

    int tid = threadIdx.x;
    int warp = tid >> 5, lane = tid & 31;
    int wm = (warp & 1) * 64;
    int wn = (warp >> 1) * 32;

    // cp.async assignments: 4 A-chunks + 4 B-chunks per thread per stage
    uint32_t aDst[4], bDst[4];
    const __half* aSrc[4];
    const __half* bSrc[4];
#pragma unroll
    for (int i = 0; i < 4; i++) {
        int idx = tid + 256 * i;            // 0..1023
        int row = idx >> 3, c = idx & 7;
        uint32_t swz = (uint32_t)(row * 128 + ((c ^ (row & 7)) * 16));
        aDst[i] = base + swz;
        bDst[i] = base + ST_A + swz;
        aSrc[i] = g_f + (size_t)(m0 + row) * KTOT + c * 8;
        bSrc[i] = g_w + (size_t)(c0 + row) * KTOT + c * 8;
    }

#define LOAD_STAGE(j) do { \
        uint32_t _so = (uint32_t)((j) % 3) * ST_STRIDE; \
        size_t _ko = (size_t)(j) * BK; \
        _Pragma("unroll") \
        for (int _i = 0; _i < 4; _i++) { \
            CPA16(aDst[_i] + _so, aSrc[_i] + _ko); \
            CPA16(bDst[_i] + _so, bSrc[_i] + _ko); \
        } \
        CP_COMMIT(); \
    } while (0)

    uint32_t xorv = lane & 7;
    uint32_t aRowOff = (uint32_t)(wm + (lane & 15)) * 128;
    uint32_t aSel = lane >> 4;
    uint32_t bRowOff = (uint32_t)(wn + ((lane >> 4) << 3) + (lane & 7)) * 128;
    uint32_t bSel = (lane >> 3) & 1;

    float acc[4][4][4];
#pragma unroll
    for (int i = 0; i < 4; i++)
#pragma unroll
        for (int j = 0; j < 4; j++)
#pragma unroll
            for (int e = 0; e < 4; e++) acc[i][j][e] = 0.f;

    LOAD_STAGE(0);
    LOAD_STAGE(1);

    for (int kt = 0; kt < KIT; kt++) {
        asm volatile("cp.async.wait_group 1;" ::: "memory");
        __syncthreads();
        if (kt + 2 < KIT) { LOAD_STAGE(kt + 2); }
        else { CP_COMMIT(); }   // keep group count uniform

        uint32_t stA = base + (uint32_t)(kt % 3) * ST_STRIDE;
        uint32_t stB = stA + ST_A;
#pragma unroll
        for (int ks = 0; ks < 4; ks++) {
            uint32_t a[4][4], b[4][2];
            uint32_t physA = ((2u * ks + aSel) ^ xorv) << 4;
            uint32_t physB = ((2u * ks + bSel) ^ xorv) << 4;
#pragma unroll
            for (int mi = 0; mi < 4; mi++)
                LDSM4(a[mi][0], a[mi][1], a[mi][2], a[mi][3],
                      stA + aRowOff + mi * 2048 + physA);
            LDSM4(b[0][0], b[0][1], b[1][0], b[1][1], stB + bRowOff + physB);
            LDSM4(b[2][0], b[2][1], b[3][0], b[3][1], stB + bRowOff + 2048 + physB);
#pragma unroll
            for (int mi = 0; mi < 4; mi++)
#pragma unroll
                for (int nj = 0; nj < 4; nj++)
                    mma16816(acc[mi][nj], a[mi], b[nj]);
        }
    }
    __syncthreads();   // stage smem reusable as epilogue staging

    // epilogue: gate in regs -> smem (stride 68) -> coalesced float4 stores
    float* ep = reinterpret_cast<float*>(sm);
    {
        int g = lane >> 2, t = lane & 3;
#pragma unroll
        for (int j = 0; j < 2; j++) {
#pragma unroll
            for (int e = 0; e < 4; e++) {
                int nl = (wn >> 1) + j * 8 + t * 2 + (e & 1);
                int n = ntile * 64 + nl;
                float bo = __ldg(bo1 + n) + __ldg(bo2 + n);
                float bg = __ldg(bg1 + n) + __ldg(bg2 + n);
#pragma unroll
                for (int mi = 0; mi < 4; mi++) {
                    int ml = wm + mi * 16 + g + ((e >> 1) * 8);
                    float o = acc[mi][j][e] + bo;
                    float gg = acc[mi][j + 2][e] + bg;
                    ep[ml * 68 + nl] = o * (1.f / (1.f + __expf(-gg)));
                }
            }
        }
    }
    __syncthreads();
    {
        float* outp = out + (size_t)m0 * OUTD + ntile * 64;
#pragma unroll
        for (int qq = 0; qq < 8; qq++) {
            int idx = tid + 256 * qq;        // 2048 float4 (128 rows x 16)
            int row = idx >> 4, c = (idx & 15) * 4;
            const float* src = ep + row * 68 + c;
            float4 v = make_float4(src[0], src[1], src[2], src[3]);
            *reinterpret_cast<float4*>(outp + (size_t)row * OUTD + c) = v;
        }
    }
#undef LOAD_STAGE
}

// ---------------------------------------------------------------------------
extern "C" void kernel_launch(void* const* d_in, const int* in_sizes, int n_in,
                              void* d_out, int out_size) {
    const float* x1  = (const float*)d_in[0];
    const float* x2  = (const float*)d_in[1];
    const float* s1  = (const float*)d_in[2];
    const float* b1  = (const float*)d_in[3];
    const float* s2  = (const float*)d_in[4];
    const float* b2  = (const float*)d_in[5];
    const float* Wo1 = (const float*)d_in[6];
    const float* bo1 = (const float*)d_in[7];
    const float* Wo2 = (const float*)d_in[8];
    const float* bo2 = (const float*)d_in[9];
    const float* Wg1 = (const float*)d_in[10];
    const float* bg1 = (const float*)d_in[11];
    const float* Wg2 = (const float*)d_in[12];
    const float* bg2 = (const float*)d_in[13];
    float* out = (float*)d_out;

    ln_act_kernel<<<B_ROWS / 8, 256>>>(x1, x2, s1, b1, s2, b2);
    pack_w_kernel<<<dim3(64, 48), 256>>>(Wo1, Wo2, Wg1, Wg2);

    cudaFuncSetAttribute(gemm_kernel,
                         cudaFuncAttributeMaxDynamicSharedMemorySize, SMEM_DYN);
    gemm_kernel<<<(B_ROWS / 128) * (NPACK / 128), 256, SMEM_DYN>>>(
        bo1, bo2, bg1, bg2, out);
}